// round 14
// baseline (speedup 1.0000x reference)
#include <cuda_runtime.h>
#include <cuda_fp16.h>
#include <math.h>

#define N_NODES 100000
#define NP1     100001
#define IN_DIM  64
#define HID     32
#define N_EDGES 1600000
#define N_GRAPH 256
#define SCAN_B  1024
#define NBLK    ((N_NODES + SCAN_B - 1) / SCAN_B)   // 98
#define WF_BLOCKS 12
#define W1_BLOCKS 8
#define SCAT_BLOCKS 800
#define D0_NODES 64
#define D0_BLOCKS ((N_NODES + D0_NODES - 1) / D0_NODES)
#define SENT_OFF (N_NODES * 8)                       // sentinel uint2-offset (r=0, zero row)

// ---------------- device scratch ----------------
__device__ __half g_relA[(size_t)3 * NP1 * HID];   // node N_NODES = zero row
__device__ __half g_relB[(size_t)3 * NP1 * HID];
__device__ float  g_aggA[N_NODES * HID];
__device__ float  g_aggB[N_NODES * HID];
__device__ int    g_deg[N_NODES];
__device__ int    g_cur[N_NODES];
__device__ int    g_rowptr[N_NODES + 2];
__device__ int    g_scanstate[NBLK];
__device__ int    g_edge_packed[N_EDGES + 1];      // precomputed (r*NP1+s)*8 uint2-offsets
// layers 2-4 weights fp16, PERMUTED k-pair layout:
// pos(l,m,k,o) = l*4096 + ((m*16 + (k>>1))*8 + (o>>2))*8 + (o&3)*2 + (k&1)
__device__ __half g_Wh[3 * 4 * HID * HID];
// layer-1 combined weights fp16: [i][f] with f = m*32+c (rel0|rel1|rel2|loop)
__device__ __half g_W1h[IN_DIM * 128];
__device__ float  g_pooled[N_GRAPH * 128];
__device__ int    g_cnt[N_GRAPH];

__device__ __forceinline__ float fast_tanh(float x) {
    float e = __expf(2.0f * x);
    return 1.0f - __fdividef(2.0f, e + 1.0f);
}

// ---------------- kernel 1: histogram ----------------
__global__ void hist_kernel(const int* __restrict__ dst) {
    const int4* d4 = (const int4*)dst;
    int i = blockIdx.x * blockDim.x + threadIdx.x;
    int stride = gridDim.x * blockDim.x;
    for (int e = i; e < N_EDGES / 4; e += stride) {
        int4 d = __ldg(&d4[e]);
        atomicAdd(&g_deg[d.x], 1);
        atomicAdd(&g_deg[d.y], 1);
        atomicAdd(&g_deg[d.z], 1);
        atomicAdd(&g_deg[d.w], 1);
    }
}

__device__ __forceinline__ int lbound(const int* __restrict__ a, int n, int key) {
    int lo = 0, hi = n;
    while (lo < hi) { int mid = (lo + hi) >> 1; if (__ldg(&a[mid]) < key) lo = mid + 1; else hi = mid; }
    return lo;
}

// ---------------- kernel 2: lookback scan + weight combines + counts + sentinel ----
__global__ void scan_kernel(const float* __restrict__ basis1,
                            const float* __restrict__ basis_r,
                            const float* __restrict__ loop1,
                            const float* __restrict__ loop_r,
                            const float* __restrict__ wcomp,
                            const int* __restrict__ gids) {
    int b = blockIdx.x;
    int t = threadIdx.x, lane = t & 31, wid = t >> 5;

    if (b >= NBLK) {
        if (b < NBLK + WF_BLOCKS) {
            int j = (b - NBLK) * SCAN_B + t;
            if (j < 3 * 4 * HID * HID) {
                int l  = j / (4 * HID * HID);
                int m  = (j / (HID * HID)) % 4;
                int io = j % (HID * HID);
                int k  = io / HID;
                int o  = io % HID;
                float v;
                if (m < 3)
                    v = wcomp[((l + 1) * 3 + m) * 2 + 0] * basis_r[(l * 2 + 0) * HID * HID + io]
                      + wcomp[((l + 1) * 3 + m) * 2 + 1] * basis_r[(l * 2 + 1) * HID * HID + io];
                else
                    v = loop_r[l * HID * HID + io];
                int pos = l * 4096 + ((m * 16 + (k >> 1)) * 8 + (o >> 2)) * 8
                        + (o & 3) * 2 + (k & 1);
                g_Wh[pos] = __float2half(v);
            }
        } else if (b < NBLK + WF_BLOCKS + W1_BLOCKS) {
            int j = (b - NBLK - WF_BLOCKS) * SCAN_B + t;   // 0..8191
            int i = j >> 7, f = j & 127;
            int m = f >> 5, c = f & 31;
            float v;
            if (m < 3)
                v = wcomp[m * 2 + 0] * basis1[0 * IN_DIM * HID + i * HID + c]
                  + wcomp[m * 2 + 1] * basis1[1 * IN_DIM * HID + i * HID + c];
            else
                v = loop1[i * HID + c];
            g_W1h[j] = __float2half(v);
        } else {
            if (t < N_GRAPH) {
                int lo = lbound(gids, N_NODES, t);
                int hi = lbound(gids, N_NODES, t + 1);
                g_cnt[t] = hi - lo;
            } else if (t == N_GRAPH) {
                g_edge_packed[N_EDGES] = SENT_OFF;   // sentinel -> zero row
                g_rowptr[N_NODES + 1] = 0;           // pad so int2/scalar reads are safe
            } else if (t >= 512 && t < 512 + 96) {
                int j = t - 512;
                int r = j >> 5, cc = j & 31;
                g_relA[((size_t)r * NP1 + N_NODES) * HID + cc] = __float2half(0.f);
                g_relB[((size_t)r * NP1 + N_NODES) * HID + cc] = __float2half(0.f);
            }
        }
        return;
    }

    __shared__ int ws[32];
    __shared__ int s_exc;
    int i = b * SCAN_B + t;
    int d = (i < N_NODES) ? g_deg[i] : 0;
    int x = d;
    #pragma unroll
    for (int o = 1; o < 32; o <<= 1) {
        int tt = __shfl_up_sync(0xffffffffu, x, o);
        if (lane >= o) x += tt;
    }
    if (lane == 31) ws[wid] = x;
    __syncthreads();
    if (wid == 0) {
        int s = ws[lane];
        #pragma unroll
        for (int o = 1; o < 32; o <<= 1) {
            int tt = __shfl_up_sync(0xffffffffu, s, o);
            if (lane >= o) s += tt;
        }
        ws[lane] = s;
    }
    __syncthreads();
    int total = ws[31];
    int pre = (wid > 0) ? ws[wid - 1] : 0;

    if (t == 0) {
        unsigned v = (b == 0) ? ((2u << 30) | (unsigned)total)
                              : ((1u << 30) | (unsigned)total);
        __threadfence();
        atomicExch(&g_scanstate[b], (int)v);
        if (b == 0) s_exc = 0;
    }
    if (b > 0 && wid == 0) {
        int excl = 0;
        int look = b - 1;
        while (true) {
            int idx = look - lane;
            unsigned st;
            if (idx >= 0) {
                do { st = (unsigned)atomicAdd(&g_scanstate[idx], 0); } while ((st >> 30) == 0);
            } else {
                st = 0x80000000u;
            }
            unsigned pf = __ballot_sync(0xffffffffu, (st >> 30) >= 2u);
            int firstp = __ffs(pf) - 1;
            int v = (int)(st & 0x3FFFFFFFu);
            int take = (firstp < 0) ? v : ((lane <= firstp) ? v : 0);
            #pragma unroll
            for (int o = 16; o > 0; o >>= 1) take += __shfl_down_sync(0xffffffffu, take, o);
            take = __shfl_sync(0xffffffffu, take, 0);
            excl += take;
            if (firstp >= 0) break;
            look -= 32;
        }
        if (lane == 0) {
            atomicExch(&g_scanstate[b], (int)((2u << 30) | (unsigned)(excl + total)));
            s_exc = excl;
        }
    }
    __syncthreads();
    int excl = s_exc + pre + (x - d);
    if (i < N_NODES) { g_rowptr[i] = excl; g_cur[i] = excl; }
    if (b == NBLK - 1 && t == SCAN_B - 1) g_rowptr[N_NODES] = excl + d;
}

// ---------------- kernel 3: scatter + dense0 ----------------
__global__ __launch_bounds__(256) void scatter_dense0_kernel(
        const int* __restrict__ src, const int* __restrict__ dst,
        const int* __restrict__ etype,
        const float* __restrict__ x,
        const float* __restrict__ bias) {
    __shared__ float sW[IN_DIM * 128];       // 32KB
    __shared__ float sx[D0_NODES * IN_DIM];  // 16KB
    int t = threadIdx.x;

    if (blockIdx.x < SCAT_BLOCKS) {
        const int4* s4 = (const int4*)src;
        const int4* d4 = (const int4*)dst;
        const int4* t4 = (const int4*)etype;
        int i = blockIdx.x * 256 + t;
        int stride = SCAT_BLOCKS * 256;
        for (int e = i; e < N_EDGES / 4; e += stride) {
            int4 s = __ldg(&s4[e]);
            int4 d = __ldg(&d4[e]);
            int4 r = __ldg(&t4[e]);
            int p;
            p = atomicAdd(&g_cur[d.x], 1); g_edge_packed[p] = (r.x * NP1 + s.x) * 8;
            p = atomicAdd(&g_cur[d.y], 1); g_edge_packed[p] = (r.y * NP1 + s.y) * 8;
            p = atomicAdd(&g_cur[d.z], 1); g_edge_packed[p] = (r.z * NP1 + s.z) * 8;
            p = atomicAdd(&g_cur[d.w], 1); g_edge_packed[p] = (r.w * NP1 + s.w) * 8;
        }
        return;
    }

    int base = (blockIdx.x - SCAT_BLOCKS) * D0_NODES;
    // fast W fill: 1024 uint4 loads of precombined fp16 W1
    {
        const uint4* w4 = (const uint4*)g_W1h;
        for (int jj = t; jj < IN_DIM * 128 / 8; jj += 256) {
            uint4 v = __ldg(&w4[jj]);
            __half2* hp = (__half2*)&v;
            float2 f0 = __half22float2(hp[0]);
            float2 f1 = __half22float2(hp[1]);
            float2 f2 = __half22float2(hp[2]);
            float2 f3 = __half22float2(hp[3]);
            float4* s4 = (float4*)&sW[jj * 8];
            s4[0] = make_float4(f0.x, f0.y, f1.x, f1.y);
            s4[1] = make_float4(f2.x, f2.y, f3.x, f3.y);
        }
    }
    {
        const float4* x4 = (const float4*)x;
        float4* sx4 = (float4*)sx;
        #pragma unroll
        for (int q = 0; q < 4; q++) {
            int idx = t + 256 * q;
            int node = idx >> 4, f4 = idx & 15;
            int gn = base + node;
            sx4[idx] = (gn < N_NODES) ? __ldg(&x4[gn * 16 + f4])
                                      : make_float4(0.f, 0.f, 0.f, 0.f);
        }
    }
    __syncthreads();
    int ng = t >> 5;
    int f = (t & 31) * 4;
    float acc[8][4];
    #pragma unroll
    for (int j = 0; j < 8; j++) { acc[j][0] = acc[j][1] = acc[j][2] = acc[j][3] = 0.f; }
    #pragma unroll 4
    for (int i = 0; i < IN_DIM; i++) {
        float4 w = *(const float4*)&sW[i * 128 + f];
        #pragma unroll
        for (int j = 0; j < 8; j++) {
            float xv = sx[(ng * 8 + j) * IN_DIM + i];
            acc[j][0] += xv * w.x;
            acc[j][1] += xv * w.y;
            acc[j][2] += xv * w.z;
            acc[j][3] += xv * w.w;
        }
    }
    int m = f >> 5, c = f & 31;
    #pragma unroll
    for (int j = 0; j < 8; j++) {
        int n = base + ng * 8 + j;
        if (n >= N_NODES) break;
        if (m < 3) {
            __half2 ha = __floats2half2_rn(acc[j][0], acc[j][1]);
            __half2 hb = __floats2half2_rn(acc[j][2], acc[j][3]);
            uint2 pk;
            pk.x = *reinterpret_cast<unsigned int*>(&ha);
            pk.y = *reinterpret_cast<unsigned int*>(&hb);
            *(uint2*)&g_relA[((size_t)m * NP1 + n) * HID + c] = pk;
        } else {
            float4 b4 = *(const float4*)&bias[c];
            *(float4*)&g_aggA[n * HID + c] =
                make_float4(acc[j][0] + b4.x, acc[j][1] + b4.y,
                            acc[j][2] + b4.z, acc[j][3] + b4.w);
        }
    }
}

// ---------------- gather: precomputed uint2-offset edges, branch-free sentinel -----
__device__ __forceinline__ void gacc2(const uint2* __restrict__ rel2,
                                      int eidx, int c, __half2& a0, __half2& a1) {
    int p = __ldg(&g_edge_packed[eidx]);
    uint2 v = __ldg(rel2 + p + c);
    a0 = __hadd2(a0, *(__half2*)&v.x);
    a1 = __hadd2(a1, *(__half2*)&v.y);
}

// returns packed per-lane partials: A0=(f0,f1), A1=(f2,f3) per node (nB = nA+1)
__device__ __forceinline__ void gather_pair_rel(const __half* __restrict__ relIn,
                                                int nA, int m, int c,
                                                __half2& A0, __half2& A1,
                                                __half2& B0, __half2& B1) {
    const uint2* rel2 = (const uint2*)relIn;
    int2 rp = __ldg((const int2*)&g_rowptr[nA]);   // nA even -> 8B aligned
    int endB = __ldg(&g_rowptr[nA + 2]);
    int kA = rp.x, kB = rp.y;
    int dA = kB - kA, dB = endB - kB;
    int mx = dA > dB ? dA : dB;
    __half2 z = __floats2half2_rn(0.f, 0.f);
    __half2 A00 = z, A01 = z, A10 = z, A11 = z;
    __half2 B00 = z, B01 = z, B10 = z, B11 = z;
    for (int base = 0; base < mx; base += 8) {
        int e0 = base + m, e1 = base + 4 + m;
        int iA0 = (e0 < dA) ? kA + e0 : N_EDGES;
        int iB0 = (e0 < dB) ? kB + e0 : N_EDGES;
        int iA1 = (e1 < dA) ? kA + e1 : N_EDGES;
        int iB1 = (e1 < dB) ? kB + e1 : N_EDGES;
        gacc2(rel2, iA0, c, A00, A01);
        gacc2(rel2, iB0, c, B00, B01);
        gacc2(rel2, iA1, c, A10, A11);
        gacc2(rel2, iB1, c, B10, B11);
    }
    A0 = __hadd2(A00, A10);
    A1 = __hadd2(A01, A11);
    B0 = __hadd2(B00, B10);
    B1 = __hadd2(B01, B11);
}

// packed half2 shfl-xor allreduce over offsets 8 and 16
__device__ __forceinline__ void reduce_h2(__half2& v) {
    unsigned int u = *reinterpret_cast<unsigned int*>(&v);
    unsigned int o = __shfl_xor_sync(0xffffffffu, u, 8);
    v = __hadd2(v, *(__half2*)&o);
    u = *reinterpret_cast<unsigned int*>(&v);
    o = __shfl_xor_sync(0xffffffffu, u, 16);
    v = __hadd2(v, *(__half2*)&o);
}

// ---------------- fused pull + tanh + pool + next-layer dense (HFMA2 matvec) -------
__global__ __launch_bounds__(256) void fused_kernel(const __half* __restrict__ relIn,
                             const float* __restrict__ aggIn,
                             __half* __restrict__ relOut,
                             float* __restrict__ aggOut,
                             const __half* __restrict__ Wh,     // permuted k-pair layout
                             const float* __restrict__ biasRow,
                             const int* __restrict__ gids,
                             int layerOff)
{
    __shared__ __align__(16) __half sW[4 * HID * HID];   // 8KB, permuted
    int tid = threadIdx.x;
    for (int i = tid; i < 4 * HID * HID / 2; i += 256)
        ((unsigned int*)sW)[i] = ((const unsigned int*)Wh)[i];
    __syncthreads();
    int warp = tid >> 5, lane = tid & 31;
    int w = blockIdx.x * 8 + warp;
    int nA = w * 2, nB = w * 2 + 1;
    int m = lane >> 3, c = lane & 7;
    __half2 A0, A1, B0, B1;
    gather_pair_rel(relIn, nA, m, c, A0, A1, B0, B1);
    reduce_h2(A0); reduce_h2(A1); reduce_h2(B0); reduce_h2(B1);
    float2 fa0 = __half22float2(A0), fa1 = __half22float2(A1);
    float2 fb0 = __half22float2(B0), fb1 = __half22float2(B1);
    float4 slA = ((const float4*)aggIn)[nA * 8 + c];
    float4 slB = ((const float4*)aggIn)[nB * 8 + c];
    float hA[4] = { fast_tanh(fa0.x + slA.x), fast_tanh(fa0.y + slA.y),
                    fast_tanh(fa1.x + slA.z), fast_tanh(fa1.y + slA.w) };
    float hB[4] = { fast_tanh(fb0.x + slB.x), fast_tanh(fb0.y + slB.y),
                    fast_tanh(fb1.x + slB.z), fast_tanh(fb1.y + slB.w) };
    if (m == 0) {
        int gA = __ldg(&gids[nA]);
        int gB = __ldg(&gids[nB]);
        if (gA == gB) {
            #pragma unroll
            for (int q = 0; q < 4; q++)
                atomicAdd(&g_pooled[gA * 128 + layerOff + c * 4 + q], hA[q] + hB[q]);
        } else {
            #pragma unroll
            for (int q = 0; q < 4; q++) {
                atomicAdd(&g_pooled[gA * 128 + layerOff + c * 4 + q], hA[q]);
                atomicAdd(&g_pooled[gB * 128 + layerOff + c * 4 + q], hB[q]);
            }
        }
    }
    // pack h as half2 k-pairs for the broadcast
    unsigned int hApk[2], hBpk[2];
    {
        __half2 p0 = __floats2half2_rn(hA[0], hA[1]);
        __half2 p1 = __floats2half2_rn(hA[2], hA[3]);
        hApk[0] = *reinterpret_cast<unsigned int*>(&p0);
        hApk[1] = *reinterpret_cast<unsigned int*>(&p1);
        p0 = __floats2half2_rn(hB[0], hB[1]);
        p1 = __floats2half2_rn(hB[2], hB[3]);
        hBpk[0] = *reinterpret_cast<unsigned int*>(&p0);
        hBpk[1] = *reinterpret_cast<unsigned int*>(&p1);
    }
    // matvec: group m computes h @ W_m, half2 dual-partial-sum accumulation
    int grp = lane & 24;
    __half2 z2 = __floats2half2_rn(0.f, 0.f);
    __half2 accA[4] = {z2, z2, z2, z2}, accB[4] = {z2, z2, z2, z2};
    const __half* sWm = sW + ((m * 16) * 8 + c) * 8;
    #pragma unroll
    for (int j = 0; j < 16; j++) {
        unsigned int hvA = __shfl_sync(0xffffffffu, hApk[j & 1], grp | (j >> 1));
        unsigned int hvB = __shfl_sync(0xffffffffu, hBpk[j & 1], grp | (j >> 1));
        uint4 wv = *(const uint4*)(sWm + j * 64);
        __half2 h2A = *(__half2*)&hvA;
        __half2 h2B = *(__half2*)&hvB;
        accA[0] = __hfma2(h2A, *(__half2*)&wv.x, accA[0]);
        accA[1] = __hfma2(h2A, *(__half2*)&wv.y, accA[1]);
        accA[2] = __hfma2(h2A, *(__half2*)&wv.z, accA[2]);
        accA[3] = __hfma2(h2A, *(__half2*)&wv.w, accA[3]);
        accB[0] = __hfma2(h2B, *(__half2*)&wv.x, accB[0]);
        accB[1] = __hfma2(h2B, *(__half2*)&wv.y, accB[1]);
        accB[2] = __hfma2(h2B, *(__half2*)&wv.z, accB[2]);
        accB[3] = __hfma2(h2B, *(__half2*)&wv.w, accB[3]);
    }
    __half oAh[4], oBh[4];
    #pragma unroll
    for (int q = 0; q < 4; q++) {
        oAh[q] = __hadd(__low2half(accA[q]), __high2half(accA[q]));
        oBh[q] = __hadd(__low2half(accB[q]), __high2half(accB[q]));
    }
    if (m < 3) {
        __half2 ha = __halves2half2(oAh[0], oAh[1]);
        __half2 hb = __halves2half2(oAh[2], oAh[3]);
        uint2 pk;
        pk.x = *reinterpret_cast<unsigned int*>(&ha);
        pk.y = *reinterpret_cast<unsigned int*>(&hb);
        ((uint2*)relOut)[((size_t)m * NP1 + nA) * 8 + c] = pk;
        ha = __halves2half2(oBh[0], oBh[1]);
        hb = __halves2half2(oBh[2], oBh[3]);
        pk.x = *reinterpret_cast<unsigned int*>(&ha);
        pk.y = *reinterpret_cast<unsigned int*>(&hb);
        ((uint2*)relOut)[((size_t)m * NP1 + nB) * 8 + c] = pk;
    } else {
        float4 b4 = ((const float4*)biasRow)[c];
        ((float4*)aggOut)[nA * 8 + c] =
            make_float4(__half2float(oAh[0]) + b4.x, __half2float(oAh[1]) + b4.y,
                        __half2float(oAh[2]) + b4.z, __half2float(oAh[3]) + b4.w);
        ((float4*)aggOut)[nB * 8 + c] =
            make_float4(__half2float(oBh[0]) + b4.x, __half2float(oBh[1]) + b4.y,
                        __half2float(oBh[2]) + b4.z, __half2float(oBh[3]) + b4.w);
    }
}

// ---------------- final: pull + tanh + pool only ----------------
__global__ __launch_bounds__(256) void final_kernel(const __half* __restrict__ relIn,
                             const float* __restrict__ aggIn,
                             const int* __restrict__ gids)
{
    int warp = threadIdx.x >> 5, lane = threadIdx.x & 31;
    int w = blockIdx.x * 8 + warp;
    int nA = w * 2, nB = w * 2 + 1;
    int m = lane >> 3, c = lane & 7;
    __half2 A0, A1, B0, B1;
    gather_pair_rel(relIn, nA, m, c, A0, A1, B0, B1);
    reduce_h2(A0); reduce_h2(A1); reduce_h2(B0); reduce_h2(B1);
    if (m == 0) {
        float2 fa0 = __half22float2(A0), fa1 = __half22float2(A1);
        float2 fb0 = __half22float2(B0), fb1 = __half22float2(B1);
        float4 slA = ((const float4*)aggIn)[nA * 8 + c];
        float4 slB = ((const float4*)aggIn)[nB * 8 + c];
        float hA[4] = { fast_tanh(fa0.x + slA.x), fast_tanh(fa0.y + slA.y),
                        fast_tanh(fa1.x + slA.z), fast_tanh(fa1.y + slA.w) };
        float hB[4] = { fast_tanh(fb0.x + slB.x), fast_tanh(fb0.y + slB.y),
                        fast_tanh(fb1.x + slB.z), fast_tanh(fb1.y + slB.w) };
        int gA = __ldg(&gids[nA]);
        int gB = __ldg(&gids[nB]);
        if (gA == gB) {
            #pragma unroll
            for (int q = 0; q < 4; q++)
                atomicAdd(&g_pooled[gA * 128 + 96 + c * 4 + q], hA[q] + hB[q]);
        } else {
            #pragma unroll
            for (int q = 0; q < 4; q++) {
                atomicAdd(&g_pooled[gA * 128 + 96 + c * 4 + q], hA[q]);
                atomicAdd(&g_pooled[gB * 128 + 96 + c * 4 + q], hB[q]);
            }
        }
    }
}

// ---------------- final MLP ----------------
__global__ void mlp_kernel(const float* __restrict__ lin1_w,
                           const float* __restrict__ lin1_b,
                           const float* __restrict__ lin2_w,
                           const float* __restrict__ lin2_b,
                           float* __restrict__ out) {
    int g = blockIdx.x;
    int k = threadIdx.x;
    __shared__ float sp[128];
    __shared__ float partial[2];
    float cnt = (float)g_cnt[g];
    float inv = 1.0f / fmaxf(cnt, 1.0f);
    sp[k]      = g_pooled[g * 128 + k] * inv;
    sp[64 + k] = g_pooled[g * 128 + 64 + k] * inv;
    __syncthreads();
    float acc = lin1_b[k];
    #pragma unroll
    for (int j = 0; j < 128; j++) acc += sp[j] * lin1_w[j * 64 + k];
    float h = fmaxf(acc, 0.0f);
    float t = h * lin2_w[k];
    #pragma unroll
    for (int o = 16; o > 0; o >>= 1) t += __shfl_down_sync(0xffffffffu, t, o);
    if ((k & 31) == 0) partial[k >> 5] = t;
    __syncthreads();
    if (k == 0) {
        float s = partial[0] + partial[1] + lin2_b[0];
        out[g] = 1.0f / (1.0f + expf(-s));
    }
}

// ---------------- launcher ----------------
extern "C" void kernel_launch(void* const* d_in, const int* in_sizes, int n_in,
                              void* d_out, int out_size) {
    const float* x       = (const float*)d_in[0];
    const float* basis1  = (const float*)d_in[1];
    const float* basis_r = (const float*)d_in[2];
    const float* w_comp  = (const float*)d_in[3];
    const float* loop1   = (const float*)d_in[4];
    const float* loop_r  = (const float*)d_in[5];
    const float* bias    = (const float*)d_in[6];
    const float* lin1_w  = (const float*)d_in[7];
    const float* lin1_b  = (const float*)d_in[8];
    const float* lin2_w  = (const float*)d_in[9];
    const float* lin2_b  = (const float*)d_in[10];
    const int*   src     = (const int*)d_in[11];
    const int*   dst     = (const int*)d_in[12];
    const int*   etype   = (const int*)d_in[13];
    const int*   gids    = (const int*)d_in[14];
    float* out = (float*)d_out;

    __half *relA, *relB, *Wh;
    float *aggA, *aggB, *pooled;
    int *deg, *scanstate;
    cudaGetSymbolAddress((void**)&relA, g_relA);
    cudaGetSymbolAddress((void**)&relB, g_relB);
    cudaGetSymbolAddress((void**)&aggA, g_aggA);
    cudaGetSymbolAddress((void**)&aggB, g_aggB);
    cudaGetSymbolAddress((void**)&Wh, g_Wh);
    cudaGetSymbolAddress((void**)&pooled, g_pooled);
    cudaGetSymbolAddress((void**)&deg, g_deg);
    cudaGetSymbolAddress((void**)&scanstate, g_scanstate);

    cudaMemsetAsync(deg, 0, N_NODES * sizeof(int));
    cudaMemsetAsync(scanstate, 0, NBLK * sizeof(int));
    cudaMemsetAsync(pooled, 0, N_GRAPH * 128 * sizeof(float));

    const int nodeBlocks = N_NODES / 16;    // 6250: 8 warps/block, 2 adjacent nodes/warp

    hist_kernel<<<800, 256>>>(dst);
    scan_kernel<<<NBLK + WF_BLOCKS + W1_BLOCKS + 1, SCAN_B>>>(basis1, basis_r, loop1,
                                                              loop_r, w_comp, gids);
    scatter_dense0_kernel<<<SCAT_BLOCKS + D0_BLOCKS, 256>>>(src, dst, etype, x, bias);
    // layer 1 -> pool cols 0-31, rel/agg for layer 2
    fused_kernel<<<nodeBlocks, 256>>>(relA, aggA, relB, aggB,
                                      Wh + 0 * 4 * HID * HID, bias + 1 * HID, gids, 0);
    // layer 2 -> pool cols 32-63
    fused_kernel<<<nodeBlocks, 256>>>(relB, aggB, relA, aggA,
                                      Wh + 1 * 4 * HID * HID, bias + 2 * HID, gids, 32);
    // layer 3 -> pool cols 64-95
    fused_kernel<<<nodeBlocks, 256>>>(relA, aggA, relB, aggB,
                                      Wh + 2 * 4 * HID * HID, bias + 3 * HID, gids, 64);
    // layer 4 -> pool cols 96-127
    final_kernel<<<nodeBlocks, 256>>>(relB, aggB, gids);
    mlp_kernel<<<N_GRAPH, 64>>>(lin1_w, lin1_b, lin2_w, lin2_b, out);
}

// round 15
// speedup vs baseline: 1.0265x; 1.0265x over previous
#include <cuda_runtime.h>
#include <cuda_fp16.h>
#include <math.h>

#define N_NODES 100000
#define NP1     100001
#define IN_DIM  64
#define HID     32
#define N_EDGES 1600000
#define N_GRAPH 256
#define SCAN_B  1024
#define NBLK    ((N_NODES + SCAN_B - 1) / SCAN_B)   // 98
#define WF_BLOCKS 12
#define W1_BLOCKS 8
#define SCAT_BLOCKS 800
#define D0_NODES 64
#define D0_BLOCKS ((N_NODES + D0_NODES - 1) / D0_NODES)
#define CONV_T  512                                  // threads per conv block (16 warps)

// ---------------- device scratch ----------------
__device__ __half g_relA[(size_t)3 * NP1 * HID];   // node N_NODES = zero row
__device__ __half g_relB[(size_t)3 * NP1 * HID];
__device__ float  g_aggA[N_NODES * HID];
__device__ float  g_aggB[N_NODES * HID];
__device__ int    g_deg[N_NODES];
__device__ int    g_cur[N_NODES];
__device__ int    g_rowptr[N_NODES + 1];
__device__ int    g_scanstate[NBLK];
__device__ int    g_edge_packed[N_EDGES + 1];      // src | (etype<<17); +1 sentinel
// layers 2-4 weights fp16, PERMUTED k-pair layout:
// pos(l,m,k,o) = l*4096 + ((m*16 + (k>>1))*8 + (o>>2))*8 + (o&3)*2 + (k&1)
__device__ __half g_Wh[3 * 4 * HID * HID];
// layer-1 combined weights fp16: [i][f] with f = m*32+c (rel0|rel1|rel2|loop)
__device__ __half g_W1h[IN_DIM * 128];
__device__ float  g_pooled[N_GRAPH * 128];
__device__ int    g_cnt[N_GRAPH];

__device__ __forceinline__ float fast_tanh(float x) {
    float e = __expf(2.0f * x);
    return 1.0f - __fdividef(2.0f, e + 1.0f);
}

// ---------------- kernel 1: histogram ----------------
__global__ void hist_kernel(const int* __restrict__ dst) {
    const int4* d4 = (const int4*)dst;
    int i = blockIdx.x * blockDim.x + threadIdx.x;
    int stride = gridDim.x * blockDim.x;
    for (int e = i; e < N_EDGES / 4; e += stride) {
        int4 d = __ldg(&d4[e]);
        atomicAdd(&g_deg[d.x], 1);
        atomicAdd(&g_deg[d.y], 1);
        atomicAdd(&g_deg[d.z], 1);
        atomicAdd(&g_deg[d.w], 1);
    }
}

__device__ __forceinline__ int lbound(const int* __restrict__ a, int n, int key) {
    int lo = 0, hi = n;
    while (lo < hi) { int mid = (lo + hi) >> 1; if (__ldg(&a[mid]) < key) lo = mid + 1; else hi = mid; }
    return lo;
}

// ---------------- kernel 2: lookback scan + weight combines + counts + sentinel ----
__global__ void scan_kernel(const float* __restrict__ basis1,
                            const float* __restrict__ basis_r,
                            const float* __restrict__ loop1,
                            const float* __restrict__ loop_r,
                            const float* __restrict__ wcomp,
                            const int* __restrict__ gids) {
    int b = blockIdx.x;
    int t = threadIdx.x, lane = t & 31, wid = t >> 5;

    if (b >= NBLK) {
        if (b < NBLK + WF_BLOCKS) {
            int j = (b - NBLK) * SCAN_B + t;
            if (j < 3 * 4 * HID * HID) {
                int l  = j / (4 * HID * HID);
                int m  = (j / (HID * HID)) % 4;
                int io = j % (HID * HID);
                int k  = io / HID;
                int o  = io % HID;
                float v;
                if (m < 3)
                    v = wcomp[((l + 1) * 3 + m) * 2 + 0] * basis_r[(l * 2 + 0) * HID * HID + io]
                      + wcomp[((l + 1) * 3 + m) * 2 + 1] * basis_r[(l * 2 + 1) * HID * HID + io];
                else
                    v = loop_r[l * HID * HID + io];
                int pos = l * 4096 + ((m * 16 + (k >> 1)) * 8 + (o >> 2)) * 8
                        + (o & 3) * 2 + (k & 1);
                g_Wh[pos] = __float2half(v);
            }
        } else if (b < NBLK + WF_BLOCKS + W1_BLOCKS) {
            int j = (b - NBLK - WF_BLOCKS) * SCAN_B + t;   // 0..8191
            int i = j >> 7, f = j & 127;
            int m = f >> 5, c = f & 31;
            float v;
            if (m < 3)
                v = wcomp[m * 2 + 0] * basis1[0 * IN_DIM * HID + i * HID + c]
                  + wcomp[m * 2 + 1] * basis1[1 * IN_DIM * HID + i * HID + c];
            else
                v = loop1[i * HID + c];
            g_W1h[j] = __float2half(v);
        } else {
            if (t < N_GRAPH) {
                int lo = lbound(gids, N_NODES, t);
                int hi = lbound(gids, N_NODES, t + 1);
                g_cnt[t] = hi - lo;
            } else if (t == N_GRAPH) {
                g_edge_packed[N_EDGES] = N_NODES;    // sentinel: r=0, src=zero row
            } else if (t >= 512 && t < 512 + 96) {
                int j = t - 512;
                int r = j >> 5, cc = j & 31;
                g_relA[((size_t)r * NP1 + N_NODES) * HID + cc] = __float2half(0.f);
                g_relB[((size_t)r * NP1 + N_NODES) * HID + cc] = __float2half(0.f);
            }
        }
        return;
    }

    __shared__ int ws[32];
    __shared__ int s_exc;
    int i = b * SCAN_B + t;
    int d = (i < N_NODES) ? g_deg[i] : 0;
    int x = d;
    #pragma unroll
    for (int o = 1; o < 32; o <<= 1) {
        int tt = __shfl_up_sync(0xffffffffu, x, o);
        if (lane >= o) x += tt;
    }
    if (lane == 31) ws[wid] = x;
    __syncthreads();
    if (wid == 0) {
        int s = ws[lane];
        #pragma unroll
        for (int o = 1; o < 32; o <<= 1) {
            int tt = __shfl_up_sync(0xffffffffu, s, o);
            if (lane >= o) s += tt;
        }
        ws[lane] = s;
    }
    __syncthreads();
    int total = ws[31];
    int pre = (wid > 0) ? ws[wid - 1] : 0;

    if (t == 0) {
        unsigned v = (b == 0) ? ((2u << 30) | (unsigned)total)
                              : ((1u << 30) | (unsigned)total);
        __threadfence();
        atomicExch(&g_scanstate[b], (int)v);
        if (b == 0) s_exc = 0;
    }
    if (b > 0 && wid == 0) {
        int excl = 0;
        int look = b - 1;
        while (true) {
            int idx = look - lane;
            unsigned st;
            if (idx >= 0) {
                do { st = (unsigned)atomicAdd(&g_scanstate[idx], 0); } while ((st >> 30) == 0);
            } else {
                st = 0x80000000u;
            }
            unsigned pf = __ballot_sync(0xffffffffu, (st >> 30) >= 2u);
            int firstp = __ffs(pf) - 1;
            int v = (int)(st & 0x3FFFFFFFu);
            int take = (firstp < 0) ? v : ((lane <= firstp) ? v : 0);
            #pragma unroll
            for (int o = 16; o > 0; o >>= 1) take += __shfl_down_sync(0xffffffffu, take, o);
            take = __shfl_sync(0xffffffffu, take, 0);
            excl += take;
            if (firstp >= 0) break;
            look -= 32;
        }
        if (lane == 0) {
            atomicExch(&g_scanstate[b], (int)((2u << 30) | (unsigned)(excl + total)));
            s_exc = excl;
        }
    }
    __syncthreads();
    int excl = s_exc + pre + (x - d);
    if (i < N_NODES) { g_rowptr[i] = excl; g_cur[i] = excl; }
    if (b == NBLK - 1 && t == SCAN_B - 1) g_rowptr[N_NODES] = excl + d;
}

// ---------------- kernel 3: scatter + dense0 ----------------
__global__ __launch_bounds__(256) void scatter_dense0_kernel(
        const int* __restrict__ src, const int* __restrict__ dst,
        const int* __restrict__ etype,
        const float* __restrict__ x,
        const float* __restrict__ bias) {
    __shared__ float sW[IN_DIM * 128];       // 32KB
    __shared__ float sx[D0_NODES * IN_DIM];  // 16KB
    int t = threadIdx.x;

    if (blockIdx.x < SCAT_BLOCKS) {
        const int4* s4 = (const int4*)src;
        const int4* d4 = (const int4*)dst;
        const int4* t4 = (const int4*)etype;
        int i = blockIdx.x * 256 + t;
        int stride = SCAT_BLOCKS * 256;
        for (int e = i; e < N_EDGES / 4; e += stride) {
            int4 s = __ldg(&s4[e]);
            int4 d = __ldg(&d4[e]);
            int4 r = __ldg(&t4[e]);
            int p;
            p = atomicAdd(&g_cur[d.x], 1); g_edge_packed[p] = s.x | (r.x << 17);
            p = atomicAdd(&g_cur[d.y], 1); g_edge_packed[p] = s.y | (r.y << 17);
            p = atomicAdd(&g_cur[d.z], 1); g_edge_packed[p] = s.z | (r.z << 17);
            p = atomicAdd(&g_cur[d.w], 1); g_edge_packed[p] = s.w | (r.w << 17);
        }
        return;
    }

    int base = (blockIdx.x - SCAT_BLOCKS) * D0_NODES;
    // fast W fill: 1024 uint4 loads of precombined fp16 W1
    {
        const uint4* w4 = (const uint4*)g_W1h;
        for (int jj = t; jj < IN_DIM * 128 / 8; jj += 256) {
            uint4 v = __ldg(&w4[jj]);
            __half2* hp = (__half2*)&v;
            float2 f0 = __half22float2(hp[0]);
            float2 f1 = __half22float2(hp[1]);
            float2 f2 = __half22float2(hp[2]);
            float2 f3 = __half22float2(hp[3]);
            float4* s4 = (float4*)&sW[jj * 8];
            s4[0] = make_float4(f0.x, f0.y, f1.x, f1.y);
            s4[1] = make_float4(f2.x, f2.y, f3.x, f3.y);
        }
    }
    {
        const float4* x4 = (const float4*)x;
        float4* sx4 = (float4*)sx;
        #pragma unroll
        for (int q = 0; q < 4; q++) {
            int idx = t + 256 * q;
            int node = idx >> 4, f4 = idx & 15;
            int gn = base + node;
            sx4[idx] = (gn < N_NODES) ? __ldg(&x4[gn * 16 + f4])
                                      : make_float4(0.f, 0.f, 0.f, 0.f);
        }
    }
    __syncthreads();
    int ng = t >> 5;
    int f = (t & 31) * 4;
    float acc[8][4];
    #pragma unroll
    for (int j = 0; j < 8; j++) { acc[j][0] = acc[j][1] = acc[j][2] = acc[j][3] = 0.f; }
    #pragma unroll 4
    for (int i = 0; i < IN_DIM; i++) {
        float4 w = *(const float4*)&sW[i * 128 + f];
        #pragma unroll
        for (int j = 0; j < 8; j++) {
            float xv = sx[(ng * 8 + j) * IN_DIM + i];
            acc[j][0] += xv * w.x;
            acc[j][1] += xv * w.y;
            acc[j][2] += xv * w.z;
            acc[j][3] += xv * w.w;
        }
    }
    int m = f >> 5, c = f & 31;
    #pragma unroll
    for (int j = 0; j < 8; j++) {
        int n = base + ng * 8 + j;
        if (n >= N_NODES) break;
        if (m < 3) {
            __half2 ha = __floats2half2_rn(acc[j][0], acc[j][1]);
            __half2 hb = __floats2half2_rn(acc[j][2], acc[j][3]);
            uint2 pk;
            pk.x = *reinterpret_cast<unsigned int*>(&ha);
            pk.y = *reinterpret_cast<unsigned int*>(&hb);
            *(uint2*)&g_relA[((size_t)m * NP1 + n) * HID + c] = pk;
        } else {
            float4 b4 = *(const float4*)&bias[c];
            *(float4*)&g_aggA[n * HID + c] =
                make_float4(acc[j][0] + b4.x, acc[j][1] + b4.y,
                            acc[j][2] + b4.z, acc[j][3] + b4.w);
        }
    }
}

// ---------------- gather: branch-free sentinel, packed half2 output (R13 shape) ----
__device__ __forceinline__ void gacc2(const __half* __restrict__ relIn,
                                      int eidx, int c, __half2& a0, __half2& a1) {
    int p = __ldg(&g_edge_packed[eidx]);
    uint2 v = __ldg((const uint2*)(relIn + ((size_t)(p >> 17) * NP1 + (p & 0x1FFFF)) * HID) + c);
    a0 = __hadd2(a0, *(__half2*)&v.x);
    a1 = __hadd2(a1, *(__half2*)&v.y);
}

// returns packed per-lane partials: A0=(f0,f1), A1=(f2,f3) per node
__device__ __forceinline__ void gather_pair_rel(const __half* __restrict__ relIn,
                                                int nA, int nB, int m, int c,
                                                __half2& A0, __half2& A1,
                                                __half2& B0, __half2& B1) {
    int kA = g_rowptr[nA], dA = g_rowptr[nA + 1] - kA;
    int kB = g_rowptr[nB], dB = g_rowptr[nB + 1] - kB;
    int mx = dA > dB ? dA : dB;
    __half2 z = __floats2half2_rn(0.f, 0.f);
    __half2 A00 = z, A01 = z, A10 = z, A11 = z;
    __half2 B00 = z, B01 = z, B10 = z, B11 = z;
    for (int base = 0; base < mx; base += 8) {
        int e0 = base + m, e1 = base + 4 + m;
        int iA0 = (e0 < dA) ? kA + e0 : N_EDGES;
        int iB0 = (e0 < dB) ? kB + e0 : N_EDGES;
        int iA1 = (e1 < dA) ? kA + e1 : N_EDGES;
        int iB1 = (e1 < dB) ? kB + e1 : N_EDGES;
        gacc2(relIn, iA0, c, A00, A01);
        gacc2(relIn, iB0, c, B00, B01);
        gacc2(relIn, iA1, c, A10, A11);
        gacc2(relIn, iB1, c, B10, B11);
    }
    A0 = __hadd2(A00, A10);
    A1 = __hadd2(A01, A11);
    B0 = __hadd2(B00, B10);
    B1 = __hadd2(B01, B11);
}

// packed half2 shfl-xor allreduce over offsets 8 and 16
__device__ __forceinline__ void reduce_h2(__half2& v) {
    unsigned int u = *reinterpret_cast<unsigned int*>(&v);
    unsigned int o = __shfl_xor_sync(0xffffffffu, u, 8);
    v = __hadd2(v, *(__half2*)&o);
    u = *reinterpret_cast<unsigned int*>(&v);
    o = __shfl_xor_sync(0xffffffffu, u, 16);
    v = __hadd2(v, *(__half2*)&o);
}

// ---------------- fused pull + tanh + pool + next-layer dense (HFMA2 matvec) -------
__global__ __launch_bounds__(CONV_T) void fused_kernel(const __half* __restrict__ relIn,
                             const float* __restrict__ aggIn,
                             __half* __restrict__ relOut,
                             float* __restrict__ aggOut,
                             const __half* __restrict__ Wh,     // permuted k-pair layout
                             const float* __restrict__ biasRow,
                             const int* __restrict__ gids,
                             int layerOff)
{
    __shared__ __align__(16) __half sW[4 * HID * HID];   // 8KB, permuted
    int tid = threadIdx.x;
    for (int i = tid; i < 4 * HID * HID / 2; i += CONV_T)
        ((unsigned int*)sW)[i] = ((const unsigned int*)Wh)[i];
    __syncthreads();
    int warp = tid >> 5, lane = tid & 31;
    int w = blockIdx.x * (CONV_T / 32) + warp;
    int nA = w * 2, nB = w * 2 + 1;
    int m = lane >> 3, c = lane & 7;
    __half2 A0, A1, B0, B1;
    gather_pair_rel(relIn, nA, nB, m, c, A0, A1, B0, B1);
    reduce_h2(A0); reduce_h2(A1); reduce_h2(B0); reduce_h2(B1);
    float2 fa0 = __half22float2(A0), fa1 = __half22float2(A1);
    float2 fb0 = __half22float2(B0), fb1 = __half22float2(B1);
    float4 slA = ((const float4*)aggIn)[nA * 8 + c];
    float4 slB = ((const float4*)aggIn)[nB * 8 + c];
    float hA[4] = { fast_tanh(fa0.x + slA.x), fast_tanh(fa0.y + slA.y),
                    fast_tanh(fa1.x + slA.z), fast_tanh(fa1.y + slA.w) };
    float hB[4] = { fast_tanh(fb0.x + slB.x), fast_tanh(fb0.y + slB.y),
                    fast_tanh(fb1.x + slB.z), fast_tanh(fb1.y + slB.w) };
    if (m == 0) {
        int gA = __ldg(&gids[nA]);
        int gB = __ldg(&gids[nB]);
        if (gA == gB) {
            #pragma unroll
            for (int q = 0; q < 4; q++)
                atomicAdd(&g_pooled[gA * 128 + layerOff + c * 4 + q], hA[q] + hB[q]);
        } else {
            #pragma unroll
            for (int q = 0; q < 4; q++) {
                atomicAdd(&g_pooled[gA * 128 + layerOff + c * 4 + q], hA[q]);
                atomicAdd(&g_pooled[gB * 128 + layerOff + c * 4 + q], hB[q]);
            }
        }
    }
    // pack h as half2 k-pairs for the broadcast
    unsigned int hApk[2], hBpk[2];
    {
        __half2 p0 = __floats2half2_rn(hA[0], hA[1]);
        __half2 p1 = __floats2half2_rn(hA[2], hA[3]);
        hApk[0] = *reinterpret_cast<unsigned int*>(&p0);
        hApk[1] = *reinterpret_cast<unsigned int*>(&p1);
        p0 = __floats2half2_rn(hB[0], hB[1]);
        p1 = __floats2half2_rn(hB[2], hB[3]);
        hBpk[0] = *reinterpret_cast<unsigned int*>(&p0);
        hBpk[1] = *reinterpret_cast<unsigned int*>(&p1);
    }
    // matvec: group m computes h @ W_m, half2 dual-partial-sum accumulation
    int grp = lane & 24;
    __half2 z2 = __floats2half2_rn(0.f, 0.f);
    __half2 accA[4] = {z2, z2, z2, z2}, accB[4] = {z2, z2, z2, z2};
    const __half* sWm = sW + ((m * 16) * 8 + c) * 8;
    #pragma unroll
    for (int j = 0; j < 16; j++) {
        unsigned int hvA = __shfl_sync(0xffffffffu, hApk[j & 1], grp | (j >> 1));
        unsigned int hvB = __shfl_sync(0xffffffffu, hBpk[j & 1], grp | (j >> 1));
        uint4 wv = *(const uint4*)(sWm + j * 64);
        __half2 h2A = *(__half2*)&hvA;
        __half2 h2B = *(__half2*)&hvB;
        accA[0] = __hfma2(h2A, *(__half2*)&wv.x, accA[0]);
        accA[1] = __hfma2(h2A, *(__half2*)&wv.y, accA[1]);
        accA[2] = __hfma2(h2A, *(__half2*)&wv.z, accA[2]);
        accA[3] = __hfma2(h2A, *(__half2*)&wv.w, accA[3]);
        accB[0] = __hfma2(h2B, *(__half2*)&wv.x, accB[0]);
        accB[1] = __hfma2(h2B, *(__half2*)&wv.y, accB[1]);
        accB[2] = __hfma2(h2B, *(__half2*)&wv.z, accB[2]);
        accB[3] = __hfma2(h2B, *(__half2*)&wv.w, accB[3]);
    }
    __half oAh[4], oBh[4];
    #pragma unroll
    for (int q = 0; q < 4; q++) {
        oAh[q] = __hadd(__low2half(accA[q]), __high2half(accA[q]));
        oBh[q] = __hadd(__low2half(accB[q]), __high2half(accB[q]));
    }
    if (m < 3) {
        __half2 ha = __halves2half2(oAh[0], oAh[1]);
        __half2 hb = __halves2half2(oAh[2], oAh[3]);
        uint2 pk;
        pk.x = *reinterpret_cast<unsigned int*>(&ha);
        pk.y = *reinterpret_cast<unsigned int*>(&hb);
        ((uint2*)relOut)[((size_t)m * NP1 + nA) * 8 + c] = pk;
        ha = __halves2half2(oBh[0], oBh[1]);
        hb = __halves2half2(oBh[2], oBh[3]);
        pk.x = *reinterpret_cast<unsigned int*>(&ha);
        pk.y = *reinterpret_cast<unsigned int*>(&hb);
        ((uint2*)relOut)[((size_t)m * NP1 + nB) * 8 + c] = pk;
    } else {
        float4 b4 = ((const float4*)biasRow)[c];
        ((float4*)aggOut)[nA * 8 + c] =
            make_float4(__half2float(oAh[0]) + b4.x, __half2float(oAh[1]) + b4.y,
                        __half2float(oAh[2]) + b4.z, __half2float(oAh[3]) + b4.w);
        ((float4*)aggOut)[nB * 8 + c] =
            make_float4(__half2float(oBh[0]) + b4.x, __half2float(oBh[1]) + b4.y,
                        __half2float(oBh[2]) + b4.z, __half2float(oBh[3]) + b4.w);
    }
}

// ---------------- final: pull + tanh + pool only ----------------
__global__ __launch_bounds__(CONV_T) void final_kernel(const __half* __restrict__ relIn,
                             const float* __restrict__ aggIn,
                             const int* __restrict__ gids)
{
    int warp = threadIdx.x >> 5, lane = threadIdx.x & 31;
    int w = blockIdx.x * (CONV_T / 32) + warp;
    int nA = w * 2, nB = w * 2 + 1;
    int m = lane >> 3, c = lane & 7;
    __half2 A0, A1, B0, B1;
    gather_pair_rel(relIn, nA, nB, m, c, A0, A1, B0, B1);
    reduce_h2(A0); reduce_h2(A1); reduce_h2(B0); reduce_h2(B1);
    if (m == 0) {
        float2 fa0 = __half22float2(A0), fa1 = __half22float2(A1);
        float2 fb0 = __half22float2(B0), fb1 = __half22float2(B1);
        float4 slA = ((const float4*)aggIn)[nA * 8 + c];
        float4 slB = ((const float4*)aggIn)[nB * 8 + c];
        float hA[4] = { fast_tanh(fa0.x + slA.x), fast_tanh(fa0.y + slA.y),
                        fast_tanh(fa1.x + slA.z), fast_tanh(fa1.y + slA.w) };
        float hB[4] = { fast_tanh(fb0.x + slB.x), fast_tanh(fb0.y + slB.y),
                        fast_tanh(fb1.x + slB.z), fast_tanh(fb1.y + slB.w) };
        int gA = __ldg(&gids[nA]);
        int gB = __ldg(&gids[nB]);
        if (gA == gB) {
            #pragma unroll
            for (int q = 0; q < 4; q++)
                atomicAdd(&g_pooled[gA * 128 + 96 + c * 4 + q], hA[q] + hB[q]);
        } else {
            #pragma unroll
            for (int q = 0; q < 4; q++) {
                atomicAdd(&g_pooled[gA * 128 + 96 + c * 4 + q], hA[q]);
                atomicAdd(&g_pooled[gB * 128 + 96 + c * 4 + q], hB[q]);
            }
        }
    }
}

// ---------------- final MLP ----------------
__global__ void mlp_kernel(const float* __restrict__ lin1_w,
                           const float* __restrict__ lin1_b,
                           const float* __restrict__ lin2_w,
                           const float* __restrict__ lin2_b,
                           float* __restrict__ out) {
    int g = blockIdx.x;
    int k = threadIdx.x;
    __shared__ float sp[128];
    __shared__ float partial[2];
    float cnt = (float)g_cnt[g];
    float inv = 1.0f / fmaxf(cnt, 1.0f);
    sp[k]      = g_pooled[g * 128 + k] * inv;
    sp[64 + k] = g_pooled[g * 128 + 64 + k] * inv;
    __syncthreads();
    float acc = lin1_b[k];
    #pragma unroll
    for (int j = 0; j < 128; j++) acc += sp[j] * lin1_w[j * 64 + k];
    float h = fmaxf(acc, 0.0f);
    float t = h * lin2_w[k];
    #pragma unroll
    for (int o = 16; o > 0; o >>= 1) t += __shfl_down_sync(0xffffffffu, t, o);
    if ((k & 31) == 0) partial[k >> 5] = t;
    __syncthreads();
    if (k == 0) {
        float s = partial[0] + partial[1] + lin2_b[0];
        out[g] = 1.0f / (1.0f + expf(-s));
    }
}

// ---------------- launcher ----------------
extern "C" void kernel_launch(void* const* d_in, const int* in_sizes, int n_in,
                              void* d_out, int out_size) {
    const float* x       = (const float*)d_in[0];
    const float* basis1  = (const float*)d_in[1];
    const float* basis_r = (const float*)d_in[2];
    const float* w_comp  = (const float*)d_in[3];
    const float* loop1   = (const float*)d_in[4];
    const float* loop_r  = (const float*)d_in[5];
    const float* bias    = (const float*)d_in[6];
    const float* lin1_w  = (const float*)d_in[7];
    const float* lin1_b  = (const float*)d_in[8];
    const float* lin2_w  = (const float*)d_in[9];
    const float* lin2_b  = (const float*)d_in[10];
    const int*   src     = (const int*)d_in[11];
    const int*   dst     = (const int*)d_in[12];
    const int*   etype   = (const int*)d_in[13];
    const int*   gids    = (const int*)d_in[14];
    float* out = (float*)d_out;

    __half *relA, *relB, *Wh;
    float *aggA, *aggB, *pooled;
    int *deg, *scanstate;
    cudaGetSymbolAddress((void**)&relA, g_relA);
    cudaGetSymbolAddress((void**)&relB, g_relB);
    cudaGetSymbolAddress((void**)&aggA, g_aggA);
    cudaGetSymbolAddress((void**)&aggB, g_aggB);
    cudaGetSymbolAddress((void**)&Wh, g_Wh);
    cudaGetSymbolAddress((void**)&pooled, g_pooled);
    cudaGetSymbolAddress((void**)&deg, g_deg);
    cudaGetSymbolAddress((void**)&scanstate, g_scanstate);

    cudaMemsetAsync(deg, 0, N_NODES * sizeof(int));
    cudaMemsetAsync(scanstate, 0, NBLK * sizeof(int));
    cudaMemsetAsync(pooled, 0, N_GRAPH * 128 * sizeof(float));

    const int convBlocks = N_NODES / (2 * (CONV_T / 32));   // 3125: 16 warps/block, 2 nodes/warp

    hist_kernel<<<800, 256>>>(dst);
    scan_kernel<<<NBLK + WF_BLOCKS + W1_BLOCKS + 1, SCAN_B>>>(basis1, basis_r, loop1,
                                                              loop_r, w_comp, gids);
    scatter_dense0_kernel<<<SCAT_BLOCKS + D0_BLOCKS, 256>>>(src, dst, etype, x, bias);
    // layer 1 -> pool cols 0-31, rel/agg for layer 2
    fused_kernel<<<convBlocks, CONV_T>>>(relA, aggA, relB, aggB,
                                         Wh + 0 * 4 * HID * HID, bias + 1 * HID, gids, 0);
    // layer 2 -> pool cols 32-63
    fused_kernel<<<convBlocks, CONV_T>>>(relB, aggB, relA, aggA,
                                         Wh + 1 * 4 * HID * HID, bias + 2 * HID, gids, 32);
    // layer 3 -> pool cols 64-95
    fused_kernel<<<convBlocks, CONV_T>>>(relA, aggA, relB, aggB,
                                         Wh + 2 * 4 * HID * HID, bias + 3 * HID, gids, 64);
    // layer 4 -> pool cols 96-127
    final_kernel<<<convBlocks, CONV_T>>>(relB, aggB, gids);
    mlp_kernel<<<N_GRAPH, 64>>>(lin1_w, lin1_b, lin2_w, lin2_b, out);
}